// round 10
// baseline (speedup 1.0000x reference)
#include <cuda_runtime.h>
#include <cstdint>

#define H   768
#define NH_ 12
#define HD_ 64
#define B_  16
#define T_  512
#define NROWS (B_ * T_)
#define SCALING 2.0f

// -------- device scratch --------
__device__ float g_xt  [(size_t)NROWS * H];   // x, tf32-rounded (all rows)
__device__ float g_xkv [(size_t)NROWS * H];   // x rows compacted by mask, tf32
__device__ float g_weff_q[H * H];
__device__ float g_weff_v[H * H];
__device__ float g_wkt [H * H];
__device__ float g_wot [H * H];
__device__ float g_q [(size_t)NROWS * H];     // (q+b)/8, rna-rounded
__device__ float g_k [(size_t)NROWS * H];     // compacted rows, rna-rounded
__device__ float g_vt[(size_t)B_ * H * T_];   // V transposed [b][d][key], rna
__device__ float g_ao[(size_t)NROWS * H];
__device__ int   g_idx[B_ * T_];
__device__ int   g_vcnt[B_];

// ============================================================
// helpers
// ============================================================
__device__ __forceinline__ float rna_tf32(float x) {
    uint32_t u;
    asm("cvt.rna.tf32.f32 %0, %1;" : "=r"(u) : "f"(x));
    return __uint_as_float(u);
}

__device__ __forceinline__ void mma_u(float* d, const uint32_t* a,
                                      uint32_t b0, uint32_t b1) {
    asm volatile(
        "mma.sync.aligned.m16n8k8.row.col.f32.tf32.tf32.f32 "
        "{%0,%1,%2,%3}, {%4,%5,%6,%7}, {%8,%9}, {%0,%1,%2,%3};"
        : "+f"(d[0]), "+f"(d[1]), "+f"(d[2]), "+f"(d[3])
        : "r"(a[0]), "r"(a[1]), "r"(a[2]), "r"(a[3]), "r"(b0), "r"(b1));
}

__device__ __forceinline__ uint32_t smem_u32(const void* p) {
    uint32_t a;
    asm("{ .reg .u64 t; cvta.to.shared.u64 t, %1; cvt.u32.u64 %0, t; }"
        : "=r"(a) : "l"(p));
    return a;
}

#define LDSM_X4(d0, d1, d2, d3, addr)                                        \
    asm volatile("ldmatrix.sync.aligned.m8n8.x4.shared.b16 {%0,%1,%2,%3}, [%4];" \
        : "=r"(d0), "=r"(d1), "=r"(d2), "=r"(d3) : "r"(addr))

__device__ __forceinline__ void cp_async16(uint32_t dst, const void* src) {
    asm volatile("cp.async.ca.shared.global [%0], [%1], 16;" :: "r"(dst), "l"(src));
}
#define CP_COMMIT() asm volatile("cp.async.commit_group;" ::: "memory")
#define CP_WAIT(n)  asm volatile("cp.async.wait_group %0;" :: "n"(n) : "memory")

// polynomial 2^t for t <= 0 (FMA pipe). rel err ~1e-5.
__device__ __forceinline__ float exp2p(float t) {
    t = fmaxf(t, -126.f);
    float fi = floorf(t);
    float f  = t - fi;
    float p  = 0.0001540353f;
    p = fmaf(p, f, 0.0013333558f);
    p = fmaf(p, f, 0.0096181291f);
    p = fmaf(p, f, 0.0555041087f);
    p = fmaf(p, f, 0.2402265070f);
    p = fmaf(p, f, 0.6931471806f);
    p = fmaf(p, f, 1.0f);
    int ei = (int)fi;
    return p * __int_as_float((ei + 127) << 23);
}
#define LOG2E 1.4426950408889634f

// ============================================================
// fused prep (vectorized): cvt x/Wk/Wo, weff q/v, compaction
// ============================================================
#define XB4   (NROWS * H / 1024)   // 6144 blocks (float4 per thread)
#define WB4   (H * H / 1024)       // 576
#define WBLK  (H * H / 256)        // 2304

__global__ __launch_bounds__(256)
void prep_kernel(const float* __restrict__ x,
                 const float* __restrict__ Wk, const float* __restrict__ Wo,
                 const float* __restrict__ Wq, const float* __restrict__ Aq,
                 const float* __restrict__ Bq,
                 const float* __restrict__ Wv, const float* __restrict__ Av,
                 const float* __restrict__ Bv,
                 const int* __restrict__ mask) {
    int bx = blockIdx.x;
    if (bx < XB4) {
        int i = bx * 256 + threadIdx.x;
        float4 v = reinterpret_cast<const float4*>(x)[i];
        v.x = rna_tf32(v.x); v.y = rna_tf32(v.y);
        v.z = rna_tf32(v.z); v.w = rna_tf32(v.w);
        reinterpret_cast<float4*>(g_xt)[i] = v;
        return;
    }
    bx -= XB4;
    if (bx < 2 * WB4) {
        const bool isK = bx < WB4;
        int i = (isK ? bx : bx - WB4) * 256 + threadIdx.x;
        float4 v = reinterpret_cast<const float4*>(isK ? Wk : Wo)[i];
        v.x = rna_tf32(v.x); v.y = rna_tf32(v.y);
        v.z = rna_tf32(v.z); v.w = rna_tf32(v.w);
        reinterpret_cast<float4*>(isK ? g_wkt : g_wot)[i] = v;
        return;
    }
    bx -= 2 * WB4;
    if (bx < 2 * WBLK) {
        const bool isQ = bx < WBLK;
        int idx = (isQ ? bx : bx - WBLK) * 256 + threadIdx.x;
        int j = idx / H, h = idx % H;
        const float* W  = isQ ? Wq : Wv;
        const float* A  = isQ ? Aq : Av;
        const float* Bm = isQ ? Bq : Bv;
        float acc = W[idx];
#pragma unroll
        for (int r = 0; r < 4; r++)
            acc = fmaf(SCALING * Bm[j * 4 + r], A[r * H + h], acc);
        (isQ ? g_weff_q : g_weff_v)[idx] = rna_tf32(acc);
        return;
    }
    bx -= 2 * WBLK;
    if (threadIdx.x < 32) {
        int b = bx;
        int lane = threadIdx.x;
        int base = 0;
        for (int c = 0; c < T_ / 32; c++) {
            int key = c * 32 + lane;
            int v = (mask[b * T_ + key] != 0);
            unsigned bal = __ballot_sync(0xffffffffu, v);
            int pos = base + __popc(bal & ((1u << lane) - 1u));
            if (v) g_idx[b * T_ + pos] = key;
            base += __popc(bal);
        }
        if (lane == 0) g_vcnt[b] = base;
    }
}

// ============================================================
// gather compacted x rows for K/V projections (tf32-rounded)
// ============================================================
__global__ __launch_bounds__(256)
void gather_kernel(const float* __restrict__ x) {
    const int b = blockIdx.y;
    const int vcnt = g_vcnt[b];
    const int r    = threadIdx.x >> 5;
    const int lane = threadIdx.x & 31;
    const int row  = blockIdx.x * 8 + r;
    if (row >= vcnt) return;
    const int grow = g_idx[b * T_ + row];
    const float* src = x + (size_t)(b * T_ + grow) * H;
    float* dst = g_xkv + (size_t)(b * T_ + row) * H;
#pragma unroll
    for (int k = 0; k < 6; k++) {
        float4 v = *reinterpret_cast<const float4*>(src + lane * 4 + k * 128);
        v.x = rna_tf32(v.x); v.y = rna_tf32(v.y);
        v.z = rna_tf32(v.z); v.w = rna_tf32(v.w);
        *reinterpret_cast<float4*>(dst + lane * 4 + k * 128) = v;
    }
}

// ============================================================
// tf32 GEMM: 128x128 CTA tile, 4 warps @ 64x64 each, BK=16,
// ldmatrix fragments, 3-stage cp.async, 1 sync/iter, 128 thr.
// qkv=1: sel 0 -> Q ((C+b)/8, rna); sel 1 -> K (rna);
//        sel 2 -> V^T into g_vt (rna). K/V early-exit past vcnt.
// qkv=0: plain C = A W^T + b (O-projection).
// ============================================================
#define PITCH 20
#define NITER (H / 16)            // 48
#define STG_FLTS (128 * PITCH)
#define STAGE_FLTS (2 * STG_FLTS)
#define GEMM_SMEM (3 * STAGE_FLTS * 4)   // 61440 B

extern __shared__ float gsm[];

__global__ __launch_bounds__(128, 1)
void gemm_mma(const float* __restrict__ A,
              const float* W0, const float* W1, const float* W2,
              const float* b0, const float* b1, const float* b2,
              float* C0, float* C1, float* C2, int qkv) {
    const int sel = blockIdx.x / 6;
    const int rowBase = blockIdx.y * 128;
    if (qkv && sel != 0 && (rowBase & (T_ - 1)) >= g_vcnt[rowBase >> 9]) return;

    const float* Aact = (qkv && sel != 0) ? g_xkv : A;
    const float* W    = (sel == 0) ? W0 : (sel == 1) ? W1 : W2;
    const float* bias = (sel == 0) ? b0 : (sel == 1) ? b1 : b2;
    float*       C    = (sel == 0) ? C0 : (sel == 1) ? C1 : C2;

    const int tid  = threadIdx.x;
    const int wid  = tid >> 5;
    const int lane = tid & 31;
    const int lr   = lane >> 2;
    const int lc   = lane & 3;
    const int colBase = (blockIdx.x % 6) * 128;
    const int mwarp = (wid & 1) * 64;
    const int nwarp = (wid >> 1) * 64;

    const uint32_t sb = smem_u32(gsm);

    int rowi[4], c4i[4];
#pragma unroll
    for (int i = 0; i < 4; i++) {
        int e = tid + i * 128;
        rowi[i] = e >> 2;
        c4i[i]  = (e & 3) << 2;
    }

    const int rpA = (lane & 15) * PITCH + ((lane >> 4) << 2);
    const int rpB = ((lane & 7) + ((lane & 16) >> 1)) * PITCH + ((lane & 8) >> 1);

    float acc[4][8][4];
#pragma unroll
    for (int mt = 0; mt < 4; mt++)
#pragma unroll
        for (int nt = 0; nt < 8; nt++)
#pragma unroll
            for (int i = 0; i < 4; i++) acc[mt][nt][i] = 0.f;

    auto load_stage = [&](int it, int st) {
        const int koff = it * 16;
        const uint32_t base = sb + (uint32_t)(st * STAGE_FLTS) * 4;
#pragma unroll
        for (int i = 0; i < 4; i++) {
            cp_async16(base + (uint32_t)(rowi[i] * PITCH + c4i[i]) * 4,
                       Aact + (size_t)(rowBase + rowi[i]) * H + koff + c4i[i]);
            cp_async16(base + (uint32_t)(STG_FLTS + rowi[i] * PITCH + c4i[i]) * 4,
                       W + (size_t)(colBase + rowi[i]) * H + koff + c4i[i]);
        }
        CP_COMMIT();
    };

    load_stage(0, 0);
    load_stage(1, 1);

    for (int it = 0; it < NITER; it++) {
        if (it + 1 < NITER) { CP_WAIT(1); } else { CP_WAIT(0); }
        __syncthreads();
        if (it + 2 < NITER) load_stage(it + 2, (it + 2) % 3);

        const uint32_t stA = sb + (uint32_t)((it % 3) * STAGE_FLTS) * 4;
        const uint32_t stW = stA + (uint32_t)STG_FLTS * 4;
#pragma unroll
        for (int ks = 0; ks < 2; ks++) {
            uint32_t af[4][4], bf[8][2];
#pragma unroll
            for (int mt = 0; mt < 4; mt++)
                LDSM_X4(af[mt][0], af[mt][1], af[mt][2], af[mt][3],
                        stA + (uint32_t)((mwarp + mt * 16) * PITCH + ks * 8 + rpA) * 4);
#pragma unroll
            for (int ntp = 0; ntp < 4; ntp++)
                LDSM_X4(bf[2 * ntp][0], bf[2 * ntp][1], bf[2 * ntp + 1][0], bf[2 * ntp + 1][1],
                        stW + (uint32_t)((nwarp + ntp * 16) * PITCH + ks * 8 + rpB) * 4);
#pragma unroll
            for (int mt = 0; mt < 4; mt++)
#pragma unroll
                for (int nt = 0; nt < 8; nt++)
                    mma_u(acc[mt][nt], af[mt], bf[nt][0], bf[nt][1]);
        }
    }

#pragma unroll
    for (int mt = 0; mt < 4; mt++) {
        const int r0 = rowBase + mwarp + mt * 16 + lr;
#pragma unroll
        for (int nt = 0; nt < 8; nt++) {
            const int c0 = colBase + nwarp + nt * 8 + lc * 2;
            const float bb0 = __ldg(&bias[c0]);
            const float bb1 = __ldg(&bias[c0 + 1]);
            if (!qkv) {
                float2 v0 = { acc[mt][nt][0] + bb0, acc[mt][nt][1] + bb1 };
                float2 v1 = { acc[mt][nt][2] + bb0, acc[mt][nt][3] + bb1 };
                *reinterpret_cast<float2*>(&C[(size_t)r0 * H + c0])       = v0;
                *reinterpret_cast<float2*>(&C[(size_t)(r0 + 8) * H + c0]) = v1;
            } else if (sel == 2) {
                // V^T: g_vt[b][d=c0][key], rna-rounded
                const int bb = r0 >> 9, key = r0 & (T_ - 1);
                float* vt = g_vt + ((size_t)bb * H + c0) * T_;
                vt[key]            = rna_tf32(acc[mt][nt][0] + bb0);
                vt[T_ + key]       = rna_tf32(acc[mt][nt][1] + bb1);
                vt[key + 8]        = rna_tf32(acc[mt][nt][2] + bb0);
                vt[T_ + key + 8]   = rna_tf32(acc[mt][nt][3] + bb1);
            } else {
                const float sc = (sel == 0) ? 0.125f : 1.0f;   // pre-scale Q by 1/8
                float2 v0 = { rna_tf32((acc[mt][nt][0] + bb0) * sc),
                              rna_tf32((acc[mt][nt][1] + bb1) * sc) };
                float2 v1 = { rna_tf32((acc[mt][nt][2] + bb0) * sc),
                              rna_tf32((acc[mt][nt][3] + bb1) * sc) };
                *reinterpret_cast<float2*>(&C[(size_t)r0 * H + c0])       = v0;
                *reinterpret_cast<float2*>(&C[(size_t)(r0 + 8) * H + c0]) = v1;
            }
        }
    }
}

// ============================================================
// Attention: all operands pre-rounded/pre-scaled; cp.async
// double-buffered K/Vt tiles; ldmatrix for Q/K/P/V fragments.
// 128 thr (4 warps), 64 q-rows/block. grid = (8, 12, 16).
// smem: sQ | sK0 | sK1 | sVt0 | sVt1 (each 64 x 68 floats)
// ============================================================
#define AP 68
#define ATILE (64 * AP)
#define ATT_SMEM (5 * ATILE * 4)   // 87040 B

extern __shared__ float asm_[];

__global__ __launch_bounds__(128)
void attn_kernel(const float* __restrict__ Q, const float* __restrict__ K,
                 const float* __restrict__ Vt, float* __restrict__ O) {
    const uint32_t aQ  = smem_u32(asm_);
    const uint32_t aKb[2] = { aQ + (uint32_t)ATILE * 4, aQ + (uint32_t)(2 * ATILE) * 4 };
    const uint32_t aVb[2] = { aQ + (uint32_t)(3 * ATILE) * 4, aQ + (uint32_t)(4 * ATILE) * 4 };

    const int qt = blockIdx.x;
    const int nh = blockIdx.y;
    const int b  = blockIdx.z;
    const int tid  = threadIdx.x;
    const int wid  = tid >> 5;
    const int lane = tid & 31;
    const int lr   = lane >> 2;
    const int lc   = lane & 3;
    const int qr   = wid * 16 + lr;

    const int rpA = (lane & 15) * AP + ((lane >> 4) << 2);
    const int rpB = ((lane & 7) + ((lane & 16) >> 1)) * AP + ((lane & 8) >> 1);

    const int vcnt   = g_vcnt[b];
    const int ntiles = (vcnt + 63) >> 6;

    const float* Qb  = Q  + (size_t)(b * T_ + qt * 64) * H + nh * HD_;
    const float* Kb  = K  + (size_t)(b * T_) * H + nh * HD_;
    const float* Vtb = Vt + ((size_t)b * H + nh * HD_) * T_;

    const int ch = tid & 15;    // 16B chunk within 64-float row
    const int rw = tid >> 4;    // base row (0..7)

    auto prefetchKV = [&](int kt, int st) {
        const int base = kt << 6;
        const uint32_t dk = aKb[st], dv = aVb[st];
#pragma unroll
        for (int i = 0; i < 8; i++) {
            const int row = rw + 8 * i;
            const int kr  = min(base + row, vcnt - 1);
            cp_async16(dk + (uint32_t)(row * AP + ch * 4) * 4,
                       Kb + (size_t)kr * H + ch * 4);
            cp_async16(dv + (uint32_t)(row * AP + ch * 4) * 4,
                       Vtb + (size_t)row * T_ + base + ch * 4);
        }
        CP_COMMIT();
    };

    // group 0: Q + tile 0
    {
#pragma unroll
        for (int i = 0; i < 8; i++) {
            const int row = rw + 8 * i;
            cp_async16(aQ + (uint32_t)(row * AP + ch * 4) * 4,
                       Qb + (size_t)row * H + ch * 4);
        }
#pragma unroll
        for (int i = 0; i < 8; i++) {
            const int row = rw + 8 * i;
            const int kr  = min(row, vcnt - 1);
            cp_async16(aKb[0] + (uint32_t)(row * AP + ch * 4) * 4,
                       Kb + (size_t)kr * H + ch * 4);
            cp_async16(aVb[0] + (uint32_t)(row * AP + ch * 4) * 4,
                       Vtb + (size_t)row * T_ + ch * 4);
        }
        CP_COMMIT();
    }
    if (ntiles > 1) prefetchKV(1, 1);
    if (ntiles > 1) { CP_WAIT(1); } else { CP_WAIT(0); }
    __syncthreads();

    uint32_t aq[8][4];
#pragma unroll
    for (int ks = 0; ks < 8; ks++)
        LDSM_X4(aq[ks][0], aq[ks][1], aq[ks][2], aq[ks][3],
                aQ + (uint32_t)(wid * 16 * AP + ks * 8 + rpA) * 4);

    float m0 = -1e30f, m1 = -1e30f, l0 = 0.f, l1 = 0.f;
    float accO[8][4];
#pragma unroll
    for (int nt = 0; nt < 8; nt++)
#pragma unroll
        for (int i = 0; i < 4; i++) accO[nt][i] = 0.f;

    for (int kt = 0; kt < ntiles; kt++) {
        const int cur = kt & 1;
        const uint32_t aK = aKb[cur];
        const uint32_t aV = aVb[cur];

        if (kt > 0) {
            if (kt + 1 < ntiles) { CP_WAIT(1); } else { CP_WAIT(0); }
            __syncthreads();
        }
        const int base = kt << 6;
        const int nval = min(64, vcnt - base);

        // S = Q K^T
        float s[8][4];
#pragma unroll
        for (int nt = 0; nt < 8; nt++)
#pragma unroll
            for (int i = 0; i < 4; i++) s[nt][i] = 0.f;
#pragma unroll
        for (int ks = 0; ks < 8; ks++) {
#pragma unroll
            for (int ntp = 0; ntp < 4; ntp++) {
                uint32_t b00, b01, b10, b11;
                LDSM_X4(b00, b01, b10, b11,
                        aK + (uint32_t)(ntp * 16 * AP + ks * 8 + rpB) * 4);
                mma_u(s[2 * ntp],     aq[ks], b00, b01);
                mma_u(s[2 * ntp + 1], aq[ks], b10, b11);
            }
        }

#pragma unroll
        for (int nt = 0; nt < 8; nt++) {
            const int c = nt * 8 + 2 * lc;
            if (c     >= nval) { s[nt][0] = -1e9f; s[nt][2] = -1e9f; }
            if (c + 1 >= nval) { s[nt][1] = -1e9f; s[nt][3] = -1e9f; }
        }

        float mx0 = s[0][0], mx1 = s[0][2];
#pragma unroll
        for (int nt = 0; nt < 8; nt++) {
            mx0 = fmaxf(mx0, fmaxf(s[nt][0], s[nt][1]));
            mx1 = fmaxf(mx1, fmaxf(s[nt][2], s[nt][3]));
        }
        mx0 = fmaxf(mx0, __shfl_xor_sync(0xffffffffu, mx0, 1));
        mx0 = fmaxf(mx0, __shfl_xor_sync(0xffffffffu, mx0, 2));
        mx1 = fmaxf(mx1, __shfl_xor_sync(0xffffffffu, mx1, 1));
        mx1 = fmaxf(mx1, __shfl_xor_sync(0xffffffffu, mx1, 2));

        float mn0 = fmaxf(m0, mx0), mn1 = fmaxf(m1, mx1);
        float cr0 = exp2p((m0 - mn0) * LOG2E);
        float cr1 = exp2p((m1 - mn1) * LOG2E);
        m0 = mn0; m1 = mn1;

        float ps0 = 0.f, ps1 = 0.f;
#pragma unroll
        for (int nt = 0; nt < 8; nt++) {
            s[nt][0] = exp2p((s[nt][0] - mn0) * LOG2E);
            s[nt][1] = exp2p((s[nt][1] - mn0) * LOG2E);
            s[nt][2] = exp2p((s[nt][2] - mn1) * LOG2E);
            s[nt][3] = exp2p((s[nt][3] - mn1) * LOG2E);
            ps0 += s[nt][0] + s[nt][1];
            ps1 += s[nt][2] + s[nt][3];
        }
        ps0 += __shfl_xor_sync(0xffffffffu, ps0, 1);
        ps0 += __shfl_xor_sync(0xffffffffu, ps0, 2);
        ps1 += __shfl_xor_sync(0xffffffffu, ps1, 1);
        ps1 += __shfl_xor_sync(0xffffffffu, ps1, 2);
        l0 = l0 * cr0 + ps0;
        l1 = l1 * cr1 + ps1;
#pragma unroll
        for (int nt = 0; nt < 8; nt++) {
            accO[nt][0] *= cr0; accO[nt][1] *= cr0;
            accO[nt][2] *= cr1; accO[nt][3] *= cr1;
        }

        __syncthreads();   // all warps done reading K tile

        // store P (rna) into this stage's K region, reload as A-fragments
        float* sP = asm_ + (1 + cur) * ATILE;
#pragma unroll
        for (int nt = 0; nt < 8; nt++) {
            const int c = nt * 8 + 2 * lc;
            float2 p0 = { rna_tf32(s[nt][0]), rna_tf32(s[nt][1]) };
            float2 p1 = { rna_tf32(s[nt][2]), rna_tf32(s[nt][3]) };
            *reinterpret_cast<float2*>(&sP[qr * AP + c])       = p0;
            *reinterpret_cast<float2*>(&sP[(qr + 8) * AP + c]) = p1;
        }
        __syncwarp();

        uint32_t ap[8][4];
#pragma unroll
        for (int ks = 0; ks < 8; ks++)
            LDSM_X4(ap[ks][0], ap[ks][1], ap[ks][2], ap[ks][3],
                    aK + (uint32_t)(wid * 16 * AP + ks * 8 + rpA) * 4);

        // O += P * V (Vt fragments via ldmatrix)
#pragma unroll
        for (int ks = 0; ks < 8; ks++) {
#pragma unroll
            for (int ntp = 0; ntp < 4; ntp++) {
                uint32_t b00, b01, b10, b11;
                LDSM_X4(b00, b01, b10, b11,
                        aV + (uint32_t)(ntp * 16 * AP + ks * 8 + rpB) * 4);
                mma_u(accO[2 * ntp],     ap[ks], b00, b01);
                mma_u(accO[2 * ntp + 1], ap[ks], b10, b11);
            }
        }

        __syncthreads();   // stage buffers free
        if (kt + 2 < ntiles) prefetchKV(kt + 2, cur);
    }

    float* Ob = O + (size_t)(b * T_ + qt * 64) * H + nh * HD_;
    const float i0 = 1.0f / l0, i1 = 1.0f / l1;
#pragma unroll
    for (int nt = 0; nt < 8; nt++) {
        const int c = nt * 8 + 2 * lc;
        float2 o0 = { rna_tf32(accO[nt][0] * i0), rna_tf32(accO[nt][1] * i0) };
        float2 o1 = { rna_tf32(accO[nt][2] * i1), rna_tf32(accO[nt][3] * i1) };
        *reinterpret_cast<float2*>(&Ob[qr * H + c])       = o0;
        *reinterpret_cast<float2*>(&Ob[(qr + 8) * H + c]) = o1;
    }
}

// ============================================================
// launch
// ============================================================
extern "C" void kernel_launch(void* const* d_in, const int* in_sizes, int n_in,
                              void* d_out, int out_size) {
    (void)in_sizes; (void)n_in; (void)out_size;
    const float* x  = (const float*)d_in[0];
    const int*  mask = (const int*) d_in[1];
    const float* Wq = (const float*)d_in[2];
    const float* bq = (const float*)d_in[3];
    const float* Aq = (const float*)d_in[4];
    const float* Bq = (const float*)d_in[5];
    const float* Wk = (const float*)d_in[6];
    const float* bk = (const float*)d_in[7];
    const float* Wv = (const float*)d_in[8];
    const float* bv = (const float*)d_in[9];
    const float* Av = (const float*)d_in[10];
    const float* Bv = (const float*)d_in[11];
    const float* Wo = (const float*)d_in[12];
    const float* bo = (const float*)d_in[13];
    float* out = (float*)d_out;

    float *pxt, *pweff_q, *pweff_v, *pwkt, *pwot, *pq, *pk, *pvt, *pao;
    cudaGetSymbolAddress((void**)&pxt, g_xt);
    cudaGetSymbolAddress((void**)&pweff_q, g_weff_q);
    cudaGetSymbolAddress((void**)&pweff_v, g_weff_v);
    cudaGetSymbolAddress((void**)&pwkt, g_wkt);
    cudaGetSymbolAddress((void**)&pwot, g_wot);
    cudaGetSymbolAddress((void**)&pq, g_q);
    cudaGetSymbolAddress((void**)&pk, g_k);
    cudaGetSymbolAddress((void**)&pvt, g_vt);
    cudaGetSymbolAddress((void**)&pao, g_ao);

    static bool attr_set = false;
    if (!attr_set) {
        cudaFuncSetAttribute(gemm_mma,
            cudaFuncAttributeMaxDynamicSharedMemorySize, GEMM_SMEM);
        cudaFuncSetAttribute(attn_kernel,
            cudaFuncAttributeMaxDynamicSharedMemorySize, ATT_SMEM);
        attr_set = true;
    }

    prep_kernel<<<XB4 + 2 * WB4 + 2 * WBLK + B_, 256>>>(
        x, Wk, Wo, Wq, Aq, Bq, Wv, Av, Bv, mask);

    gather_kernel<<<dim3(64, B_), 256>>>(x);

    // Q over all rows; K/V over compacted rows with early exit; V written ^T
    gemm_mma<<<dim3(18, NROWS / 128), 128, GEMM_SMEM>>>(
        pxt, pweff_q, pwkt, pweff_v, bq, bk, bv, pq, pk, pvt, 1);

    attn_kernel<<<dim3(T_ / 64, NH_, B_), 128, ATT_SMEM>>>(pq, pk, pvt, pao);

    gemm_mma<<<dim3(6, NROWS / 128), 128, GEMM_SMEM>>>(
        pao, pwot, pwot, pwot, bo, bo, bo, out, out, out, 0);
}

// round 11
// speedup vs baseline: 1.0597x; 1.0597x over previous
#include <cuda_runtime.h>
#include <cstdint>

#define H   768
#define NH_ 12
#define HD_ 64
#define B_  16
#define T_  512
#define NROWS (B_ * T_)
#define SCALING 2.0f

// -------- device scratch --------
__device__ float g_xt  [(size_t)NROWS * H];   // x, tf32-rounded (all rows)
__device__ float g_xkv [(size_t)NROWS * H];   // x rows compacted by mask, tf32
__device__ float g_weff_q[H * H];
__device__ float g_weff_v[H * H];
__device__ float g_wkt [H * H];
__device__ float g_wot [H * H];
__device__ float g_q [(size_t)NROWS * H];     // (q+b)/8, rna-rounded
__device__ float g_k [(size_t)NROWS * H];     // compacted rows, rna-rounded
__device__ float g_vt[(size_t)B_ * H * T_];   // V transposed [b][d][key], rna
__device__ float g_ao[(size_t)NROWS * H];
__device__ int   g_idx[B_ * T_];
__device__ int   g_vcnt[B_];

// ============================================================
// helpers
// ============================================================
__device__ __forceinline__ float rna_tf32(float x) {
    uint32_t u;
    asm("cvt.rna.tf32.f32 %0, %1;" : "=r"(u) : "f"(x));
    return __uint_as_float(u);
}

__device__ __forceinline__ void mma_u(float* d, const uint32_t* a,
                                      uint32_t b0, uint32_t b1) {
    asm volatile(
        "mma.sync.aligned.m16n8k8.row.col.f32.tf32.tf32.f32 "
        "{%0,%1,%2,%3}, {%4,%5,%6,%7}, {%8,%9}, {%0,%1,%2,%3};"
        : "+f"(d[0]), "+f"(d[1]), "+f"(d[2]), "+f"(d[3])
        : "r"(a[0]), "r"(a[1]), "r"(a[2]), "r"(a[3]), "r"(b0), "r"(b1));
}

__device__ __forceinline__ uint32_t smem_u32(const void* p) {
    uint32_t a;
    asm("{ .reg .u64 t; cvta.to.shared.u64 t, %1; cvt.u32.u64 %0, t; }"
        : "=r"(a) : "l"(p));
    return a;
}

#define LDSM_X4(d0, d1, d2, d3, addr)                                        \
    asm volatile("ldmatrix.sync.aligned.m8n8.x4.shared.b16 {%0,%1,%2,%3}, [%4];" \
        : "=r"(d0), "=r"(d1), "=r"(d2), "=r"(d3) : "r"(addr))

__device__ __forceinline__ void cp_async16(uint32_t dst, const void* src) {
    asm volatile("cp.async.ca.shared.global [%0], [%1], 16;" :: "r"(dst), "l"(src));
}
#define CP_COMMIT() asm volatile("cp.async.commit_group;" ::: "memory")
#define CP_WAIT(n)  asm volatile("cp.async.wait_group %0;" :: "n"(n) : "memory")

// polynomial 2^t for t <= 0 (FMA pipe). rel err ~1e-5.
__device__ __forceinline__ float exp2p(float t) {
    t = fmaxf(t, -126.f);
    float fi = floorf(t);
    float f  = t - fi;
    float p  = 0.0001540353f;
    p = fmaf(p, f, 0.0013333558f);
    p = fmaf(p, f, 0.0096181291f);
    p = fmaf(p, f, 0.0555041087f);
    p = fmaf(p, f, 0.2402265070f);
    p = fmaf(p, f, 0.6931471806f);
    p = fmaf(p, f, 1.0f);
    int ei = (int)fi;
    return p * __int_as_float((ei + 127) << 23);
}
#define LOG2E 1.4426950408889634f

// ============================================================
// fused prep (vectorized): cvt x/Wk/Wo, weff q/v, compaction
// ============================================================
#define XB4   (NROWS * H / 1024)   // 6144 blocks (float4 per thread)
#define WB4   (H * H / 1024)       // 576
#define WBLK  (H * H / 256)        // 2304

__global__ __launch_bounds__(256)
void prep_kernel(const float* __restrict__ x,
                 const float* __restrict__ Wk, const float* __restrict__ Wo,
                 const float* __restrict__ Wq, const float* __restrict__ Aq,
                 const float* __restrict__ Bq,
                 const float* __restrict__ Wv, const float* __restrict__ Av,
                 const float* __restrict__ Bv,
                 const int* __restrict__ mask) {
    int bx = blockIdx.x;
    if (bx < XB4) {
        int i = bx * 256 + threadIdx.x;
        float4 v = reinterpret_cast<const float4*>(x)[i];
        v.x = rna_tf32(v.x); v.y = rna_tf32(v.y);
        v.z = rna_tf32(v.z); v.w = rna_tf32(v.w);
        reinterpret_cast<float4*>(g_xt)[i] = v;
        return;
    }
    bx -= XB4;
    if (bx < 2 * WB4) {
        const bool isK = bx < WB4;
        int i = (isK ? bx : bx - WB4) * 256 + threadIdx.x;
        float4 v = reinterpret_cast<const float4*>(isK ? Wk : Wo)[i];
        v.x = rna_tf32(v.x); v.y = rna_tf32(v.y);
        v.z = rna_tf32(v.z); v.w = rna_tf32(v.w);
        reinterpret_cast<float4*>(isK ? g_wkt : g_wot)[i] = v;
        return;
    }
    bx -= 2 * WB4;
    if (bx < 2 * WBLK) {
        const bool isQ = bx < WBLK;
        int idx = (isQ ? bx : bx - WBLK) * 256 + threadIdx.x;
        int j = idx / H, h = idx % H;
        const float* W  = isQ ? Wq : Wv;
        const float* A  = isQ ? Aq : Av;
        const float* Bm = isQ ? Bq : Bv;
        float acc = W[idx];
#pragma unroll
        for (int r = 0; r < 4; r++)
            acc = fmaf(SCALING * Bm[j * 4 + r], A[r * H + h], acc);
        (isQ ? g_weff_q : g_weff_v)[idx] = rna_tf32(acc);
        return;
    }
    bx -= 2 * WBLK;
    if (threadIdx.x < 32) {
        int b = bx;
        int lane = threadIdx.x;
        int base = 0;
        for (int c = 0; c < T_ / 32; c++) {
            int key = c * 32 + lane;
            int v = (mask[b * T_ + key] != 0);
            unsigned bal = __ballot_sync(0xffffffffu, v);
            int pos = base + __popc(bal & ((1u << lane) - 1u));
            if (v) g_idx[b * T_ + pos] = key;
            base += __popc(bal);
        }
        if (lane == 0) g_vcnt[b] = base;
    }
}

// ============================================================
// gather compacted x rows for K/V projections (tf32-rounded)
// ============================================================
__global__ __launch_bounds__(256)
void gather_kernel(const float* __restrict__ x) {
    const int b = blockIdx.y;
    const int vcnt = g_vcnt[b];
    const int r    = threadIdx.x >> 5;
    const int lane = threadIdx.x & 31;
    const int row  = blockIdx.x * 8 + r;
    if (row >= vcnt) return;
    const int grow = g_idx[b * T_ + row];
    const float* src = x + (size_t)(b * T_ + grow) * H;
    float* dst = g_xkv + (size_t)(b * T_ + row) * H;
#pragma unroll
    for (int k = 0; k < 6; k++) {
        float4 v = *reinterpret_cast<const float4*>(src + lane * 4 + k * 128);
        v.x = rna_tf32(v.x); v.y = rna_tf32(v.y);
        v.z = rna_tf32(v.z); v.w = rna_tf32(v.w);
        *reinterpret_cast<float4*>(dst + lane * 4 + k * 128) = v;
    }
}

// ============================================================
// tf32 GEMM: 128x128 CTA tile, 4 warps @ 64x64 each, BK=16,
// ldmatrix fragments, 3-stage cp.async, 1 sync/iter, 128 thr.
// qkv=1: sel 0 -> Q ((C+b)/8, rna); sel 1 -> K (rna);
//        sel 2 -> V^T into g_vt (rna). K/V early-exit past vcnt.
// qkv=0: plain C = A W^T + b (O-projection).
// ============================================================
#define PITCH 20
#define NITER (H / 16)            // 48
#define STG_FLTS (128 * PITCH)
#define STAGE_FLTS (2 * STG_FLTS)
#define GEMM_SMEM (3 * STAGE_FLTS * 4)   // 61440 B

extern __shared__ float gsm[];

__global__ __launch_bounds__(128, 1)
void gemm_mma(const float* __restrict__ A,
              const float* W0, const float* W1, const float* W2,
              const float* b0, const float* b1, const float* b2,
              float* C0, float* C1, float* C2, int qkv) {
    const int sel = blockIdx.x / 6;
    const int rowBase = blockIdx.y * 128;
    if (qkv && sel != 0 && (rowBase & (T_ - 1)) >= g_vcnt[rowBase >> 9]) return;

    const float* Aact = (qkv && sel != 0) ? g_xkv : A;
    const float* W    = (sel == 0) ? W0 : (sel == 1) ? W1 : W2;
    const float* bias = (sel == 0) ? b0 : (sel == 1) ? b1 : b2;
    float*       C    = (sel == 0) ? C0 : (sel == 1) ? C1 : C2;

    const int tid  = threadIdx.x;
    const int wid  = tid >> 5;
    const int lane = tid & 31;
    const int lr   = lane >> 2;
    const int lc   = lane & 3;
    const int colBase = (blockIdx.x % 6) * 128;
    const int mwarp = (wid & 1) * 64;
    const int nwarp = (wid >> 1) * 64;

    const uint32_t sb = smem_u32(gsm);

    int rowi[4], c4i[4];
#pragma unroll
    for (int i = 0; i < 4; i++) {
        int e = tid + i * 128;
        rowi[i] = e >> 2;
        c4i[i]  = (e & 3) << 2;
    }

    const int rpA = (lane & 15) * PITCH + ((lane >> 4) << 2);
    const int rpB = ((lane & 7) + ((lane & 16) >> 1)) * PITCH + ((lane & 8) >> 1);

    float acc[4][8][4];
#pragma unroll
    for (int mt = 0; mt < 4; mt++)
#pragma unroll
        for (int nt = 0; nt < 8; nt++)
#pragma unroll
            for (int i = 0; i < 4; i++) acc[mt][nt][i] = 0.f;

    auto load_stage = [&](int it, int st) {
        const int koff = it * 16;
        const uint32_t base = sb + (uint32_t)(st * STAGE_FLTS) * 4;
#pragma unroll
        for (int i = 0; i < 4; i++) {
            cp_async16(base + (uint32_t)(rowi[i] * PITCH + c4i[i]) * 4,
                       Aact + (size_t)(rowBase + rowi[i]) * H + koff + c4i[i]);
            cp_async16(base + (uint32_t)(STG_FLTS + rowi[i] * PITCH + c4i[i]) * 4,
                       W + (size_t)(colBase + rowi[i]) * H + koff + c4i[i]);
        }
        CP_COMMIT();
    };

    load_stage(0, 0);
    load_stage(1, 1);

    for (int it = 0; it < NITER; it++) {
        if (it + 1 < NITER) { CP_WAIT(1); } else { CP_WAIT(0); }
        __syncthreads();
        if (it + 2 < NITER) load_stage(it + 2, (it + 2) % 3);

        const uint32_t stA = sb + (uint32_t)((it % 3) * STAGE_FLTS) * 4;
        const uint32_t stW = stA + (uint32_t)STG_FLTS * 4;
#pragma unroll
        for (int ks = 0; ks < 2; ks++) {
            uint32_t af[4][4], bf[8][2];
#pragma unroll
            for (int mt = 0; mt < 4; mt++)
                LDSM_X4(af[mt][0], af[mt][1], af[mt][2], af[mt][3],
                        stA + (uint32_t)((mwarp + mt * 16) * PITCH + ks * 8 + rpA) * 4);
#pragma unroll
            for (int ntp = 0; ntp < 4; ntp++)
                LDSM_X4(bf[2 * ntp][0], bf[2 * ntp][1], bf[2 * ntp + 1][0], bf[2 * ntp + 1][1],
                        stW + (uint32_t)((nwarp + ntp * 16) * PITCH + ks * 8 + rpB) * 4);
#pragma unroll
            for (int mt = 0; mt < 4; mt++)
#pragma unroll
                for (int nt = 0; nt < 8; nt++)
                    mma_u(acc[mt][nt], af[mt], bf[nt][0], bf[nt][1]);
        }
    }

#pragma unroll
    for (int mt = 0; mt < 4; mt++) {
        const int r0 = rowBase + mwarp + mt * 16 + lr;
#pragma unroll
        for (int nt = 0; nt < 8; nt++) {
            const int c0 = colBase + nwarp + nt * 8 + lc * 2;
            const float bb0 = __ldg(&bias[c0]);
            const float bb1 = __ldg(&bias[c0 + 1]);
            if (!qkv) {
                float2 v0 = { acc[mt][nt][0] + bb0, acc[mt][nt][1] + bb1 };
                float2 v1 = { acc[mt][nt][2] + bb0, acc[mt][nt][3] + bb1 };
                *reinterpret_cast<float2*>(&C[(size_t)r0 * H + c0])       = v0;
                *reinterpret_cast<float2*>(&C[(size_t)(r0 + 8) * H + c0]) = v1;
            } else if (sel == 2) {
                // V^T: g_vt[b][d=c0][key], rna-rounded
                const int bb = r0 >> 9, key = r0 & (T_ - 1);
                float* vt = g_vt + ((size_t)bb * H + c0) * T_;
                vt[key]            = rna_tf32(acc[mt][nt][0] + bb0);
                vt[T_ + key]       = rna_tf32(acc[mt][nt][1] + bb1);
                vt[key + 8]        = rna_tf32(acc[mt][nt][2] + bb0);
                vt[T_ + key + 8]   = rna_tf32(acc[mt][nt][3] + bb1);
            } else {
                const float sc = (sel == 0) ? 0.125f : 1.0f;   // pre-scale Q by 1/8
                float2 v0 = { rna_tf32((acc[mt][nt][0] + bb0) * sc),
                              rna_tf32((acc[mt][nt][1] + bb1) * sc) };
                float2 v1 = { rna_tf32((acc[mt][nt][2] + bb0) * sc),
                              rna_tf32((acc[mt][nt][3] + bb1) * sc) };
                *reinterpret_cast<float2*>(&C[(size_t)r0 * H + c0])       = v0;
                *reinterpret_cast<float2*>(&C[(size_t)(r0 + 8) * H + c0]) = v1;
            }
        }
    }
}

// ============================================================
// Attention v5: single-buffered K/V (52 KB smem -> 4 CTA/SM),
// P reuses the dead sQ region, K(kt+1) prefetch overlaps P*V.
// All operands pre-rounded/pre-scaled; ldmatrix everywhere.
// 128 thr (4 warps), 64 q-rows/block. grid = (8, 12, 16).
// smem: sQ/sP | sK | sVt (each 64 x 68 floats)
// ============================================================
#define AP 68
#define ATILE (64 * AP)
#define ATT_SMEM (3 * ATILE * 4)   // 52224 B

extern __shared__ float asm_[];

__global__ __launch_bounds__(128, 4)
void attn_kernel(const float* __restrict__ Q, const float* __restrict__ K,
                 const float* __restrict__ Vt, float* __restrict__ O) {
    const uint32_t aQ = smem_u32(asm_);           // Q, then P
    const uint32_t aK = aQ + (uint32_t)ATILE * 4;
    const uint32_t aV = aQ + (uint32_t)(2 * ATILE) * 4;
    float* sP = asm_;                              // alias of sQ region

    const int qt = blockIdx.x;
    const int nh = blockIdx.y;
    const int b  = blockIdx.z;
    const int tid  = threadIdx.x;
    const int wid  = tid >> 5;
    const int lane = tid & 31;
    const int lr   = lane >> 2;
    const int lc   = lane & 3;
    const int qr   = wid * 16 + lr;

    const int rpA = (lane & 15) * AP + ((lane >> 4) << 2);
    const int rpB = ((lane & 7) + ((lane & 16) >> 1)) * AP + ((lane & 8) >> 1);

    const int vcnt   = g_vcnt[b];
    const int ntiles = (vcnt + 63) >> 6;

    const float* Qb  = Q  + (size_t)(b * T_ + qt * 64) * H + nh * HD_;
    const float* Kb  = K  + (size_t)(b * T_) * H + nh * HD_;
    const float* Vtb = Vt + ((size_t)b * H + nh * HD_) * T_;

    const int ch = tid & 15;    // 16B chunk within 64-float row
    const int rw = tid >> 4;    // base row (0..7)

    auto prefetchK = [&](int kt) {
        const int base = kt << 6;
#pragma unroll
        for (int i = 0; i < 8; i++) {
            const int row = rw + 8 * i;
            const int kr  = min(base + row, vcnt - 1);
            cp_async16(aK + (uint32_t)(row * AP + ch * 4) * 4,
                       Kb + (size_t)kr * H + ch * 4);
        }
        CP_COMMIT();
    };
    auto prefetchV = [&](int kt) {
        const int base = kt << 6;
#pragma unroll
        for (int i = 0; i < 8; i++) {
            const int row = rw + 8 * i;   // row = d within head
            cp_async16(aV + (uint32_t)(row * AP + ch * 4) * 4,
                       Vtb + (size_t)row * T_ + base + ch * 4);
        }
        CP_COMMIT();
    };

    // initial: Q + K0 + V0
    {
#pragma unroll
        for (int i = 0; i < 8; i++) {
            const int row = rw + 8 * i;
            cp_async16(aQ + (uint32_t)(row * AP + ch * 4) * 4,
                       Qb + (size_t)row * H + ch * 4);
        }
        CP_COMMIT();
        prefetchK(0);
        prefetchV(0);
        CP_WAIT(0);
        __syncthreads();
    }

    // preload Q fragments; sQ region becomes P scratch afterwards
    uint32_t aq[8][4];
#pragma unroll
    for (int ks = 0; ks < 8; ks++)
        LDSM_X4(aq[ks][0], aq[ks][1], aq[ks][2], aq[ks][3],
                aQ + (uint32_t)(wid * 16 * AP + ks * 8 + rpA) * 4);

    float m0 = -1e30f, m1 = -1e30f, l0 = 0.f, l1 = 0.f;
    float accO[8][4];
#pragma unroll
    for (int nt = 0; nt < 8; nt++)
#pragma unroll
        for (int i = 0; i < 4; i++) accO[nt][i] = 0.f;

    for (int kt = 0; kt < ntiles; kt++) {
        const int base = kt << 6;
        const int nval = min(64, vcnt - base);
        const bool more = (kt + 1 < ntiles);

        // S = Q K^T
        float s[8][4];
#pragma unroll
        for (int nt = 0; nt < 8; nt++)
#pragma unroll
            for (int i = 0; i < 4; i++) s[nt][i] = 0.f;
#pragma unroll
        for (int ks = 0; ks < 8; ks++) {
#pragma unroll
            for (int ntp = 0; ntp < 4; ntp++) {
                uint32_t b00, b01, b10, b11;
                LDSM_X4(b00, b01, b10, b11,
                        aK + (uint32_t)(ntp * 16 * AP + ks * 8 + rpB) * 4);
                mma_u(s[2 * ntp],     aq[ks], b00, b01);
                mma_u(s[2 * ntp + 1], aq[ks], b10, b11);
            }
        }

#pragma unroll
        for (int nt = 0; nt < 8; nt++) {
            const int c = nt * 8 + 2 * lc;
            if (c     >= nval) { s[nt][0] = -1e9f; s[nt][2] = -1e9f; }
            if (c + 1 >= nval) { s[nt][1] = -1e9f; s[nt][3] = -1e9f; }
        }

        float mx0 = s[0][0], mx1 = s[0][2];
#pragma unroll
        for (int nt = 0; nt < 8; nt++) {
            mx0 = fmaxf(mx0, fmaxf(s[nt][0], s[nt][1]));
            mx1 = fmaxf(mx1, fmaxf(s[nt][2], s[nt][3]));
        }
        mx0 = fmaxf(mx0, __shfl_xor_sync(0xffffffffu, mx0, 1));
        mx0 = fmaxf(mx0, __shfl_xor_sync(0xffffffffu, mx0, 2));
        mx1 = fmaxf(mx1, __shfl_xor_sync(0xffffffffu, mx1, 1));
        mx1 = fmaxf(mx1, __shfl_xor_sync(0xffffffffu, mx1, 2));

        float mn0 = fmaxf(m0, mx0), mn1 = fmaxf(m1, mx1);
        float cr0 = exp2p((m0 - mn0) * LOG2E);
        float cr1 = exp2p((m1 - mn1) * LOG2E);
        m0 = mn0; m1 = mn1;

        float ps0 = 0.f, ps1 = 0.f;
#pragma unroll
        for (int nt = 0; nt < 8; nt++) {
            s[nt][0] = exp2p((s[nt][0] - mn0) * LOG2E);
            s[nt][1] = exp2p((s[nt][1] - mn0) * LOG2E);
            s[nt][2] = exp2p((s[nt][2] - mn1) * LOG2E);
            s[nt][3] = exp2p((s[nt][3] - mn1) * LOG2E);
            ps0 += s[nt][0] + s[nt][1];
            ps1 += s[nt][2] + s[nt][3];
        }
        ps0 += __shfl_xor_sync(0xffffffffu, ps0, 1);
        ps0 += __shfl_xor_sync(0xffffffffu, ps0, 2);
        ps1 += __shfl_xor_sync(0xffffffffu, ps1, 1);
        ps1 += __shfl_xor_sync(0xffffffffu, ps1, 2);
        l0 = l0 * cr0 + ps0;
        l1 = l1 * cr1 + ps1;
#pragma unroll
        for (int nt = 0; nt < 8; nt++) {
            accO[nt][0] *= cr0; accO[nt][1] *= cr0;
            accO[nt][2] *= cr1; accO[nt][3] *= cr1;
        }

        __syncthreads();            // all warps done reading sK
        if (more) prefetchK(kt + 1);   // overlaps with P-store + P*V below

        // store P (rna) into sP (dead sQ region), reload as A-fragments
#pragma unroll
        for (int nt = 0; nt < 8; nt++) {
            const int c = nt * 8 + 2 * lc;
            float2 p0 = { rna_tf32(s[nt][0]), rna_tf32(s[nt][1]) };
            float2 p1 = { rna_tf32(s[nt][2]), rna_tf32(s[nt][3]) };
            *reinterpret_cast<float2*>(&sP[qr * AP + c])       = p0;
            *reinterpret_cast<float2*>(&sP[(qr + 8) * AP + c]) = p1;
        }
        __syncwarp();

        uint32_t ap[8][4];
#pragma unroll
        for (int ks = 0; ks < 8; ks++)
            LDSM_X4(ap[ks][0], ap[ks][1], ap[ks][2], ap[ks][3],
                    aQ + (uint32_t)(wid * 16 * AP + ks * 8 + rpA) * 4);

        // O += P * V (Vt fragments via ldmatrix)
#pragma unroll
        for (int ks = 0; ks < 8; ks++) {
#pragma unroll
            for (int ntp = 0; ntp < 4; ntp++) {
                uint32_t b00, b01, b10, b11;
                LDSM_X4(b00, b01, b10, b11,
                        aV + (uint32_t)(ntp * 16 * AP + ks * 8 + rpB) * 4);
                mma_u(accO[2 * ntp],     ap[ks], b00, b01);
                mma_u(accO[2 * ntp + 1], ap[ks], b10, b11);
            }
        }

        if (more) {
            __syncthreads();        // all warps done reading sV
            prefetchV(kt + 1);
            CP_WAIT(0);             // K(kt+1) and V(kt+1) both landed
            __syncthreads();
        }
    }

    float* Ob = O + (size_t)(b * T_ + qt * 64) * H + nh * HD_;
    const float i0 = 1.0f / l0, i1 = 1.0f / l1;
#pragma unroll
    for (int nt = 0; nt < 8; nt++) {
        const int c = nt * 8 + 2 * lc;
        float2 o0 = { rna_tf32(accO[nt][0] * i0), rna_tf32(accO[nt][1] * i0) };
        float2 o1 = { rna_tf32(accO[nt][2] * i1), rna_tf32(accO[nt][3] * i1) };
        *reinterpret_cast<float2*>(&Ob[qr * H + c])       = o0;
        *reinterpret_cast<float2*>(&Ob[(qr + 8) * H + c]) = o1;
    }
}

// ============================================================
// launch
// ============================================================
extern "C" void kernel_launch(void* const* d_in, const int* in_sizes, int n_in,
                              void* d_out, int out_size) {
    (void)in_sizes; (void)n_in; (void)out_size;
    const float* x  = (const float*)d_in[0];
    const int*  mask = (const int*) d_in[1];
    const float* Wq = (const float*)d_in[2];
    const float* bq = (const float*)d_in[3];
    const float* Aq = (const float*)d_in[4];
    const float* Bq = (const float*)d_in[5];
    const float* Wk = (const float*)d_in[6];
    const float* bk = (const float*)d_in[7];
    const float* Wv = (const float*)d_in[8];
    const float* bv = (const float*)d_in[9];
    const float* Av = (const float*)d_in[10];
    const float* Bv = (const float*)d_in[11];
    const float* Wo = (const float*)d_in[12];
    const float* bo = (const float*)d_in[13];
    float* out = (float*)d_out;

    float *pxt, *pweff_q, *pweff_v, *pwkt, *pwot, *pq, *pk, *pvt, *pao;
    cudaGetSymbolAddress((void**)&pxt, g_xt);
    cudaGetSymbolAddress((void**)&pweff_q, g_weff_q);
    cudaGetSymbolAddress((void**)&pweff_v, g_weff_v);
    cudaGetSymbolAddress((void**)&pwkt, g_wkt);
    cudaGetSymbolAddress((void**)&pwot, g_wot);
    cudaGetSymbolAddress((void**)&pq, g_q);
    cudaGetSymbolAddress((void**)&pk, g_k);
    cudaGetSymbolAddress((void**)&pvt, g_vt);
    cudaGetSymbolAddress((void**)&pao, g_ao);

    static bool attr_set = false;
    if (!attr_set) {
        cudaFuncSetAttribute(gemm_mma,
            cudaFuncAttributeMaxDynamicSharedMemorySize, GEMM_SMEM);
        cudaFuncSetAttribute(attn_kernel,
            cudaFuncAttributeMaxDynamicSharedMemorySize, ATT_SMEM);
        attr_set = true;
    }

    prep_kernel<<<XB4 + 2 * WB4 + 2 * WBLK + B_, 256>>>(
        x, Wk, Wo, Wq, Aq, Bq, Wv, Av, Bv, mask);

    gather_kernel<<<dim3(64, B_), 256>>>(x);

    // Q over all rows; K/V over compacted rows with early exit; V written ^T
    gemm_mma<<<dim3(18, NROWS / 128), 128, GEMM_SMEM>>>(
        pxt, pweff_q, pwkt, pweff_v, bq, bk, bv, pq, pk, pvt, 1);

    attn_kernel<<<dim3(T_ / 64, NH_, B_), 128, ATT_SMEM>>>(pq, pk, pvt, pao);

    gemm_mma<<<dim3(6, NROWS / 128), 128, GEMM_SMEM>>>(
        pao, pwot, pwot, pwot, bo, bo, bo, out, out, out, 0);
}